// round 7
// baseline (speedup 1.0000x reference)
#include <cuda_runtime.h>
#include <cuda_bf16.h>
#include <math.h>
#include <stdint.h>

// Problem constants
#define BB 4
#define TT 1024
#define DD 1024
#define HH 16
#define HDIM 64
#define LL 8
#define VV 50257
#define VPAD 50304
#define ROWS (BB*TT)            // 4096
#define SCALE_ATT 0.07216878364870322f  // 1/sqrt(192)

// ---------------------------------------------------------------------------
// Scratch (static device globals; no runtime allocation)
// ---------------------------------------------------------------------------
__device__ float g_x   [ (size_t)ROWS * DD     ];   // residual stream (fp32)
__device__ float g_qkv [ (size_t)ROWS * 3 * DD ];   // qkv (fp32)
__device__ float g_nll [ ROWS ];
// bf16 hi/lo split activations
__device__ __nv_bfloat16 g_hhi [ (size_t)ROWS * DD ];
__device__ __nv_bfloat16 g_hlo [ (size_t)ROWS * DD ];
__device__ __nv_bfloat16 g_yhi [ (size_t)ROWS * DD ];
__device__ __nv_bfloat16 g_ylo [ (size_t)ROWS * DD ];
__device__ __nv_bfloat16 g_mhi [ (size_t)ROWS * 4 * DD ];
__device__ __nv_bfloat16 g_mlo [ (size_t)ROWS * 4 * DD ];
// bf16 hi/lo split transposed weights ([N,K] row-major)
__device__ __nv_bfloat16 g_wqkvThi [ (size_t)LL * 3*DD * DD ];
__device__ __nv_bfloat16 g_wqkvTlo [ (size_t)LL * 3*DD * DD ];
__device__ __nv_bfloat16 g_wprojThi[ (size_t)LL * DD * DD ];
__device__ __nv_bfloat16 g_wprojTlo[ (size_t)LL * DD * DD ];
__device__ __nv_bfloat16 g_w1Thi   [ (size_t)LL * 4*DD * DD ];
__device__ __nv_bfloat16 g_w1Tlo   [ (size_t)LL * 4*DD * DD ];
__device__ __nv_bfloat16 g_w2Thi   [ (size_t)LL * DD * 4*DD ];
__device__ __nv_bfloat16 g_w2Tlo   [ (size_t)LL * DD * 4*DD ];
// int8 LM head (Ozaki 2-slice)
__device__ signed char g_xq1 [ (size_t)ROWS * DD ];
__device__ signed char g_xq2 [ (size_t)ROWS * DD ];
__device__ float       g_sa  [ ROWS ];
__device__ signed char g_lmq1[ (size_t)VPAD * DD ];
__device__ signed char g_lmq2[ (size_t)VPAD * DD ];
__device__ float       g_sb  [ VPAD ];

// ---------------------------------------------------------------------------
// helpers
// ---------------------------------------------------------------------------
__device__ __forceinline__ uint32_t smem_u32(const void* p) {
    uint32_t a;
    asm("{ .reg .u64 t; cvta.to.shared.u64 t, %1; cvt.u32.u64 %0, t; }"
        : "=r"(a) : "l"(p));
    return a;
}
__device__ __forceinline__ uint32_t pack2_hi(float x, float y, float& rx, float& ry) {
    __nv_bfloat16 hx = __float2bfloat16_rn(x);
    __nv_bfloat16 hy = __float2bfloat16_rn(y);
    rx = x - __bfloat162float(hx);
    ry = y - __bfloat162float(hy);
    return (uint32_t)__bfloat16_as_ushort(hx) | ((uint32_t)__bfloat16_as_ushort(hy) << 16);
}
__device__ __forceinline__ uint32_t pack2(float x, float y) {
    __nv_bfloat16 hx = __float2bfloat16_rn(x);
    __nv_bfloat16 hy = __float2bfloat16_rn(y);
    return (uint32_t)__bfloat16_as_ushort(hx) | ((uint32_t)__bfloat16_as_ushort(hy) << 16);
}

#define MMA_BF16(d, a, b) \
    asm volatile("mma.sync.aligned.m16n8k16.row.col.f32.bf16.bf16.f32 " \
        "{%0,%1,%2,%3}, {%4,%5,%6,%7}, {%8,%9}, {%0,%1,%2,%3};" \
        : "+f"((d)[0]), "+f"((d)[1]), "+f"((d)[2]), "+f"((d)[3]) \
        : "r"((a)[0]), "r"((a)[1]), "r"((a)[2]), "r"((a)[3]), \
          "r"((b)[0]), "r"((b)[1]))

#define MMA_S8(d, a, b) \
    asm volatile("mma.sync.aligned.m16n8k32.row.col.s32.s8.s8.s32 " \
        "{%0,%1,%2,%3}, {%4,%5,%6,%7}, {%8,%9}, {%0,%1,%2,%3};" \
        : "+r"((d)[0]), "+r"((d)[1]), "+r"((d)[2]), "+r"((d)[3]) \
        : "r"((a)[0]), "r"((a)[1]), "r"((a)[2]), "r"((a)[3]), \
          "r"((b)[0]), "r"((b)[1]))

#define LDSM4(r0, r1, r2, r3, addr) \
    asm volatile("ldmatrix.sync.aligned.m8n8.x4.shared.b16 {%0,%1,%2,%3}, [%4];" \
        : "=r"(r0), "=r"(r1), "=r"(r2), "=r"(r3) : "r"(addr))

__device__ __forceinline__ void cp16(uint32_t d, const void* g) {
    asm volatile("cp.async.cg.shared.global [%0], [%1], 16;" :: "r"(d), "l"(g));
}
#define CP_COMMIT() asm volatile("cp.async.commit_group;" ::: "memory")
#define CP_WAIT0()  asm volatile("cp.async.wait_group 0;" ::: "memory")
#define CP_WAIT1()  asm volatile("cp.async.wait_group 1;" ::: "memory")

// ---------------------------------------------------------------------------
// bf16-split tensor GEMM (layers): C = A @ Bt^T, pre-split bf16 hi/lo.
// ---------------------------------------------------------------------------
#define TILEB 10240
#define BUFB  (4*TILEB)        // 40960
#define SMEM_DYN (3*BUFB)      // 122880

template<int EPI>
__global__ __launch_bounds__(256) void hgemm_kernel(
    int M, int N, int K,
    const __nv_bfloat16* __restrict__ Ahi, const __nv_bfloat16* __restrict__ Alo,
    const __nv_bfloat16* __restrict__ Bhi, const __nv_bfloat16* __restrict__ Blo,
    const float* __restrict__ bias, const float* __restrict__ res,
    float* __restrict__ C,
    __nv_bfloat16* __restrict__ Chi, __nv_bfloat16* __restrict__ Clo)
{
    extern __shared__ __align__(128) char smem[];
    const uint32_t sb = smem_u32(smem);
    const int tid  = threadIdx.x;
    const int wid  = tid >> 5;
    const int lane = tid & 31;
    const int mbase = blockIdx.x * 128;
    const int nbase = blockIdx.y * 128;
    const int warp_m = wid & 1;
    const int warp_n = wid >> 1;
    const int g = lane >> 2;
    const int q = lane & 3;

    const uint32_t aoff = (uint32_t)(warp_m*64 + (lane & 15)) * 80
                        + ((lane >> 4) & 1) * 16;
    const uint32_t boff = 2*TILEB
                        + (uint32_t)(warp_n*32 + (lane & 7) + ((lane >> 4) & 1)*8) * 80
                        + ((lane >> 3) & 1) * 16;

    float acc[4][4][4];
    #pragma unroll
    for (int m = 0; m < 4; m++)
        #pragma unroll
        for (int n = 0; n < 4; n++)
            #pragma unroll
            for (int r = 0; r < 4; r++) acc[m][n][r] = 0.0f;

    const int nch = K >> 5;

    auto issue = [&](uint32_t dstbase, int k0) {
        #pragma unroll
        for (int i = 0; i < 8; i++) {
            const int tile = i >> 1;
            int v   = (i & 1) * 256 + tid;
            int row = v >> 2, seg = v & 3;
            const __nv_bfloat16* src =
                (tile == 0) ? Ahi : (tile == 1) ? Alo : (tile == 2) ? Bhi : Blo;
            int grow = ((tile < 2) ? mbase : nbase) + row;
            cp16(dstbase + tile*TILEB + (uint32_t)row*80 + seg*16,
                 src + (size_t)grow*K + k0 + seg*8);
        }
    };

    issue(sb, 0);
    CP_COMMIT();
    if (nch > 1) { issue(sb + BUFB, 32); CP_COMMIT(); }

    for (int it = 0; it < nch; it++) {
        if (it < nch - 1) { CP_WAIT1(); } else { CP_WAIT0(); }
        __syncthreads();
        if (it + 2 < nch) {
            issue(sb + (uint32_t)((it+2) % 3) * BUFB, (it+2) << 5);
            CP_COMMIT();
        }

        const uint32_t bufu = sb + (uint32_t)(it % 3) * BUFB;

        #pragma unroll
        for (int ks = 0; ks < 32; ks += 16) {
            uint32_t ah[4][4], al[4][4], bh[4][2], bl[4][2];
            #pragma unroll
            for (int m = 0; m < 4; m++) {
                uint32_t ad = bufu + aoff + m*(16*80) + ks*2;
                LDSM4(ah[m][0], ah[m][1], ah[m][2], ah[m][3], ad);
                LDSM4(al[m][0], al[m][1], al[m][2], al[m][3], ad + TILEB);
            }
            #pragma unroll
            for (int n2 = 0; n2 < 2; n2++) {
                uint32_t bd = bufu + boff + n2*(16*80) + ks*2;
                uint32_t r0, r1, r2, r3;
                LDSM4(r0, r1, r2, r3, bd);
                bh[n2*2][0] = r0; bh[n2*2][1] = r1;
                bh[n2*2+1][0] = r2; bh[n2*2+1][1] = r3;
                LDSM4(r0, r1, r2, r3, bd + TILEB);
                bl[n2*2][0] = r0; bl[n2*2][1] = r1;
                bl[n2*2+1][0] = r2; bl[n2*2+1][1] = r3;
            }
            #pragma unroll
            for (int m = 0; m < 4; m++)
                #pragma unroll
                for (int n = 0; n < 4; n++) {
                    MMA_BF16(acc[m][n], ah[m], bh[n]);
                    MMA_BF16(acc[m][n], ah[m], bl[n]);
                    MMA_BF16(acc[m][n], al[m], bh[n]);
                }
        }
    }
    __syncthreads();

    float* Cs = (float*)smem;   // [128][132]
    #pragma unroll
    for (int m = 0; m < 4; m++) {
        int r0 = warp_m*64 + m*16 + g;
        #pragma unroll
        for (int n = 0; n < 4; n++) {
            int col = warp_n*32 + n*8 + 2*q;
            Cs[r0*132 + col]       = acc[m][n][0];
            Cs[r0*132 + col + 1]   = acc[m][n][1];
            Cs[(r0+8)*132 + col]   = acc[m][n][2];
            Cs[(r0+8)*132 + col+1] = acc[m][n][3];
        }
    }
    __syncthreads();

    if (EPI == 1) {
        #pragma unroll
        for (int i = 0; i < 16; i++) {
            int u = tid + i*256;
            int row = u >> 5, c4 = (u & 31) * 4;
            int col = nbase + c4;
            float v0 = Cs[row*132 + c4 + 0] + bias[col];
            float v1 = Cs[row*132 + c4 + 1] + bias[col+1];
            float v2 = Cs[row*132 + c4 + 2] + bias[col+2];
            float v3 = Cs[row*132 + c4 + 3] + bias[col+3];
            v0 = fmaxf(v0, 0.f); v1 = fmaxf(v1, 0.f);
            v2 = fmaxf(v2, 0.f); v3 = fmaxf(v3, 0.f);
            float r0, r1, r2, r3;
            uint2 hi, lo;
            hi.x = pack2_hi(v0, v1, r0, r1);
            hi.y = pack2_hi(v2, v3, r2, r3);
            lo.x = pack2(r0, r1); lo.y = pack2(r2, r3);
            size_t off = (size_t)(mbase+row)*N + col;
            *(uint2*)(Chi + off) = hi;
            *(uint2*)(Clo + off) = lo;
        }
    } else {
        #pragma unroll
        for (int i = 0; i < 16; i++) {
            int u = tid + i*256;
            int row = u >> 5, c4 = (u & 31) * 4;
            int col = nbase + c4;
            float v0 = Cs[row*132 + c4 + 0];
            float v1 = Cs[row*132 + c4 + 1];
            float v2 = Cs[row*132 + c4 + 2];
            float v3 = Cs[row*132 + c4 + 3];
            if (bias) { v0 += bias[col]; v1 += bias[col+1]; v2 += bias[col+2]; v3 += bias[col+3]; }
            if (EPI == 2) {
                const float4 rv = *(const float4*)(res + (size_t)(mbase+row)*N + col);
                v0 += rv.x; v1 += rv.y; v2 += rv.z; v3 += rv.w;
            }
            *(float4*)(C + (size_t)(mbase+row)*N + col) = make_float4(v0, v1, v2, v3);
        }
    }
}

// ---------------------------------------------------------------------------
// int8 Ozaki GEMM (LM head): logits = x @ lmwT^T, x/w as 2 int8 slices with
// per-row scales. C[i,j] = sa_i*sb_j*(P11 + (P12+P21)/128). K-chunk 64,
// 3-stage cp.async, plain conflict-free LDS.32 fragment loads.
// smem per buffer: Aq1|Aq2|Bq1|Bq2, each 128 rows x 80B (64 payload + 16 pad)
// ---------------------------------------------------------------------------
#define ITILE 10240
#define IBUF  (4*ITILE)
#define SMEM_I (3*IBUF)        // 122880

__global__ __launch_bounds__(256) void igemm_kernel(
    int M, int N, int K,       // K in bytes/elems (1024)
    const signed char* __restrict__ Aq1, const signed char* __restrict__ Aq2,
    const signed char* __restrict__ Bq1, const signed char* __restrict__ Bq2,
    const float* __restrict__ sa, const float* __restrict__ sbv,
    float* __restrict__ C)
{
    extern __shared__ __align__(128) char smem[];
    const uint32_t sb = smem_u32(smem);
    const int tid  = threadIdx.x;
    const int wid  = tid >> 5;
    const int lane = tid & 31;
    const int mbase = blockIdx.x * 128;
    const int nbase = blockIdx.y * 128;
    const int warp_m = wid & 1;
    const int warp_n = wid >> 1;
    const int g = lane >> 2;
    const int q = lane & 3;

    int P11[4][4][4], P12[4][4][4];
    #pragma unroll
    for (int m = 0; m < 4; m++)
        #pragma unroll
        for (int n = 0; n < 4; n++)
            #pragma unroll
            for (int r = 0; r < 4; r++) { P11[m][n][r] = 0; P12[m][n][r] = 0; }

    const int nch = K >> 6;    // 16

    auto issue = [&](uint32_t dstbase, int k0) {
        #pragma unroll
        for (int i = 0; i < 8; i++) {
            const int tile = i >> 1;                 // 0:Aq1 1:Aq2 2:Bq1 3:Bq2
            int v   = (i & 1) * 256 + tid;
            int row = v >> 2, seg = v & 3;
            const signed char* src =
                (tile == 0) ? Aq1 : (tile == 1) ? Aq2 : (tile == 2) ? Bq1 : Bq2;
            int grow = ((tile < 2) ? mbase : nbase) + row;
            cp16(dstbase + tile*ITILE + (uint32_t)row*80 + seg*16,
                 src + (size_t)grow*K + k0 + seg*16);
        }
    };

    issue(sb, 0);
    CP_COMMIT();
    if (nch > 1) { issue(sb + IBUF, 64); CP_COMMIT(); }

    for (int it = 0; it < nch; it++) {
        if (it < nch - 1) { CP_WAIT1(); } else { CP_WAIT0(); }
        __syncthreads();
        if (it + 2 < nch) {
            issue(sb + (uint32_t)((it+2) % 3) * IBUF, (it+2) << 6);
            CP_COMMIT();
        }

        const char* buf = smem + (it % 3) * IBUF;

        #pragma unroll
        for (int ks = 0; ks < 64; ks += 32) {
            uint32_t a1[4][4], a2[4][4], b1[4][2], b2[4][2];
            #pragma unroll
            for (int mf = 0; mf < 4; mf++) {
                const char* pa = buf + (uint32_t)(warp_m*64 + mf*16 + g)*80 + ks + 4*q;
                a1[mf][0] = *(const uint32_t*)(pa);
                a1[mf][1] = *(const uint32_t*)(pa + 8*80);
                a1[mf][2] = *(const uint32_t*)(pa + 16);
                a1[mf][3] = *(const uint32_t*)(pa + 8*80 + 16);
                const char* pl = pa + ITILE;
                a2[mf][0] = *(const uint32_t*)(pl);
                a2[mf][1] = *(const uint32_t*)(pl + 8*80);
                a2[mf][2] = *(const uint32_t*)(pl + 16);
                a2[mf][3] = *(const uint32_t*)(pl + 8*80 + 16);
            }
            #pragma unroll
            for (int nf = 0; nf < 4; nf++) {
                const char* pb = buf + 2*ITILE + (uint32_t)(warp_n*32 + nf*8 + g)*80 + ks + 4*q;
                b1[nf][0] = *(const uint32_t*)(pb);
                b1[nf][1] = *(const uint32_t*)(pb + 16);
                const char* pl = pb + ITILE;
                b2[nf][0] = *(const uint32_t*)(pl);
                b2[nf][1] = *(const uint32_t*)(pl + 16);
            }
            #pragma unroll
            for (int mf = 0; mf < 4; mf++)
                #pragma unroll
                for (int nf = 0; nf < 4; nf++) {
                    MMA_S8(P11[mf][nf], a1[mf], b1[nf]);
                    MMA_S8(P12[mf][nf], a1[mf], b2[nf]);
                    MMA_S8(P12[mf][nf], a2[mf], b1[nf]);
                }
        }
    }
    __syncthreads();

    float* Cs = (float*)smem;   // [128][132]
    #pragma unroll
    for (int mf = 0; mf < 4; mf++) {
        int r0 = warp_m*64 + mf*16 + g;
        #pragma unroll
        for (int nf = 0; nf < 4; nf++) {
            int col = warp_n*32 + nf*8 + 2*q;
            Cs[r0*132 + col]       = (float)P11[mf][nf][0] + (float)P12[mf][nf][0] * 0.0078125f;
            Cs[r0*132 + col + 1]   = (float)P11[mf][nf][1] + (float)P12[mf][nf][1] * 0.0078125f;
            Cs[(r0+8)*132 + col]   = (float)P11[mf][nf][2] + (float)P12[mf][nf][2] * 0.0078125f;
            Cs[(r0+8)*132 + col+1] = (float)P11[mf][nf][3] + (float)P12[mf][nf][3] * 0.0078125f;
        }
    }
    __syncthreads();

    #pragma unroll
    for (int i = 0; i < 16; i++) {
        int u = tid + i*256;
        int row = u >> 5, c4 = (u & 31) * 4;
        float sA = sa[mbase + row];
        float* crow = C + (size_t)(mbase+row)*N;
        #pragma unroll
        for (int j = 0; j < 4; j++) {
            int col = nbase + c4 + j;
            if (col < N) crow[col] = Cs[row*132 + c4 + j] * sA * sbv[col];
        }
    }
}

// ---------------------------------------------------------------------------
// Tiled transpose + bf16 split (layer weights): [K,N] -> hi/lo [Npad,K]
// ---------------------------------------------------------------------------
__global__ __launch_bounds__(256) void tp_kernel(
    const float* __restrict__ in,
    __nv_bfloat16* __restrict__ outhi, __nv_bfloat16* __restrict__ outlo,
    int K, int N, int Npad, size_t inStride, size_t outStride)
{
    __shared__ float t[32][33];
    const float* ip = in + blockIdx.z * inStride;
    __nv_bfloat16* ohi = outhi + blockIdx.z * outStride;
    __nv_bfloat16* olo = outlo + blockIdx.z * outStride;
    int n0 = blockIdx.x * 32, k0 = blockIdx.y * 32;
    int tx = threadIdx.x & 31, ty = threadIdx.x >> 5;
    #pragma unroll
    for (int j = ty; j < 32; j += 8) {
        int k = k0 + j, n = n0 + tx;
        t[j][tx] = (k < K && n < N) ? ip[(size_t)k * N + n] : 0.0f;
    }
    __syncthreads();
    #pragma unroll
    for (int j = ty; j < 32; j += 8) {
        int n = n0 + j, k = k0 + tx;
        if (n < Npad && k < K) {
            float v = t[tx][j];
            __nv_bfloat16 h = __float2bfloat16_rn(v);
            __nv_bfloat16 l = __float2bfloat16_rn(v - __bfloat162float(h));
            ohi[(size_t)n * K + k] = h;
            olo[(size_t)n * K + k] = l;
        }
    }
}

// ---------------------------------------------------------------------------
// Per-column abs-max of lmw [K=DD, N=VV] -> sb[VPAD]
// ---------------------------------------------------------------------------
__global__ __launch_bounds__(256) void colscale_kernel(
    const float* __restrict__ w, float* __restrict__ sbv)
{
    int n = blockIdx.x * 256 + threadIdx.x;
    if (n >= VPAD) return;
    float m = 0.0f;
    if (n < VV) {
        for (int k = 0; k < DD; k++)
            m = fmaxf(m, fabsf(w[(size_t)k * VV + n]));
    }
    sbv[n] = m * (1.0f/127.0f) + 1e-30f;
}

// ---------------------------------------------------------------------------
// Transpose + int8 2-slice quantize: lmw [K,VV] -> q1,q2 [VPAD,K]
// ---------------------------------------------------------------------------
__global__ __launch_bounds__(256) void tpq_kernel(
    const float* __restrict__ in,
    signed char* __restrict__ o1, signed char* __restrict__ o2,
    const float* __restrict__ sbv)
{
    __shared__ float t[32][33];
    int n0 = blockIdx.x * 32, k0 = blockIdx.y * 32;
    int tx = threadIdx.x & 31, ty = threadIdx.x >> 5;
    #pragma unroll
    for (int j = ty; j < 32; j += 8) {
        int k = k0 + j, n = n0 + tx;
        t[j][tx] = (n < VV) ? in[(size_t)k * VV + n] : 0.0f;
    }
    __syncthreads();
    #pragma unroll
    for (int j = ty; j < 32; j += 8) {
        int n = n0 + j, k = k0 + tx;
        float s = sbv[n];
        float inv = 1.0f / s;
        float v = t[tx][j];
        int q1 = __float2int_rn(v * inv);
        float r = v - (float)q1 * s;
        int q2 = __float2int_rn(r * inv * 128.0f);
        o1[(size_t)n * DD + k] = (signed char)q1;
        o2[(size_t)n * DD + k] = (signed char)q2;
    }
}

// ---------------------------------------------------------------------------
// Per-row int8 2-slice quantize of residual x (LM head input)
// ---------------------------------------------------------------------------
__global__ __launch_bounds__(256) void rowquant_kernel(
    const float* __restrict__ x,
    signed char* __restrict__ q1o, signed char* __restrict__ q2o,
    float* __restrict__ sa)
{
    __shared__ float red[256];
    int row = blockIdx.x, tid = threadIdx.x;
    float4 v = ((const float4*)(x + (size_t)row * DD))[tid];
    float m = fmaxf(fmaxf(fabsf(v.x), fabsf(v.y)), fmaxf(fabsf(v.z), fabsf(v.w)));
    red[tid] = m; __syncthreads();
    for (int o = 128; o > 0; o >>= 1) {
        if (tid < o) red[tid] = fmaxf(red[tid], red[tid + o]);
        __syncthreads();
    }
    float s = red[0] * (1.0f/127.0f) + 1e-30f;
    if (tid == 0) sa[row] = s;
    float inv = 1.0f / s;
    int a0 = __float2int_rn(v.x * inv); float r0 = v.x - (float)a0 * s;
    int a1 = __float2int_rn(v.y * inv); float r1 = v.y - (float)a1 * s;
    int a2 = __float2int_rn(v.z * inv); float r2 = v.z - (float)a2 * s;
    int a3 = __float2int_rn(v.w * inv); float r3 = v.w - (float)a3 * s;
    int b0 = __float2int_rn(r0 * inv * 128.0f);
    int b1 = __float2int_rn(r1 * inv * 128.0f);
    int b2 = __float2int_rn(r2 * inv * 128.0f);
    int b3 = __float2int_rn(r3 * inv * 128.0f);
    size_t off = (size_t)row * DD + tid * 4;
    *(char4*)(q1o + off) = make_char4((signed char)a0, (signed char)a1,
                                      (signed char)a2, (signed char)a3);
    *(char4*)(q2o + off) = make_char4((signed char)b0, (signed char)b1,
                                      (signed char)b2, (signed char)b3);
}

// ---------------------------------------------------------------------------
// Embedding
// ---------------------------------------------------------------------------
__global__ __launch_bounds__(256) void embed_kernel(
    const int* __restrict__ idx, const float* __restrict__ tok,
    const float* __restrict__ pos, float* __restrict__ x)
{
    int row = blockIdx.x;
    int t   = row & (TT - 1);
    int id  = idx[row];
    const float4* tp = (const float4*)(tok + (size_t)id * DD);
    const float4* pp = (const float4*)(pos + (size_t)t  * DD);
    float4*       xp = (float4*)(x + (size_t)row * DD);
    int i = threadIdx.x;
    float4 a = tp[i], b = pp[i];
    a.x += b.x; a.y += b.y; a.z += b.z; a.w += b.w;
    xp[i] = a;
}

// ---------------------------------------------------------------------------
// LayerNorm -> bf16 hi/lo split output
// ---------------------------------------------------------------------------
__global__ __launch_bounds__(256) void ln_kernel(
    const float* __restrict__ x, const float* __restrict__ g,
    const float* __restrict__ b,
    __nv_bfloat16* __restrict__ ohi, __nv_bfloat16* __restrict__ olo)
{
    __shared__ float s1[256];
    __shared__ float s2[256];
    int row = blockIdx.x;
    int tid = threadIdx.x;
    float4 v = ((const float4*)(x + (size_t)row * DD))[tid];
    float s  = v.x + v.y + v.z + v.w;
    float ss = v.x*v.x + v.y*v.y + v.z*v.z + v.w*v.w;
    s1[tid] = s; s2[tid] = ss;
    __syncthreads();
    for (int o = 128; o > 0; o >>= 1) {
        if (tid < o) { s1[tid] += s1[tid+o]; s2[tid] += s2[tid+o]; }
        __syncthreads();
    }
    float mu   = s1[0] * (1.0f / DD);
    float var  = s2[0] * (1.0f / DD) - mu * mu;
    float rstd = rsqrtf(var + 1e-5f);
    float4 gv = ((const float4*)g)[tid];
    float4 bv = ((const float4*)b)[tid];
    float o0 = (v.x - mu) * rstd * gv.x + bv.x;
    float o1 = (v.y - mu) * rstd * gv.y + bv.y;
    float o2 = (v.z - mu) * rstd * gv.z + bv.z;
    float o3 = (v.w - mu) * rstd * gv.w + bv.w;
    float r0, r1, r2, r3;
    uint2 hi, lo;
    hi.x = pack2_hi(o0, o1, r0, r1);
    hi.y = pack2_hi(o2, o3, r2, r3);
    lo.x = pack2(r0, r1); lo.y = pack2(r2, r3);
    size_t off = (size_t)row * DD + tid * 4;
    *(uint2*)(ohi + off) = hi;
    *(uint2*)(olo + off) = lo;
}

// ---------------------------------------------------------------------------
// Fused causal attention (R6 version: 16-key branchless tiles)
// ---------------------------------------------------------------------------
__global__ __launch_bounds__(128) void attn_kernel(
    const float* __restrict__ qkv,
    __nv_bfloat16* __restrict__ yhi, __nv_bfloat16* __restrict__ ylo)
{
    const int bh = blockIdx.x;
    const int b  = bh >> 4;
    const int h  = bh & (HH - 1);
    const int t  = blockIdx.y * 128 + threadIdx.x;
    const int row = b * TT + t;
    const int wid = threadIdx.x >> 5;

    __shared__ float Kt[64][HDIM];
    __shared__ float Vt[64][HDIM];

    float4 qv[16];
    {
        const float4* qp = (const float4*)(qkv + (size_t)row * (3*DD) + h * HDIM);
        #pragma unroll
        for (int i = 0; i < 16; i++) qv[i] = qp[i];
    }

    float4 acc[16];
    #pragma unroll
    for (int i = 0; i < 16; i++) acc[i] = make_float4(0.f, 0.f, 0.f, 0.f);
    float m = -1e30f, l = 0.0f;

    const int kmax = blockIdx.y * 128 + 127;
    const int warp_tmax = blockIdx.y * 128 + wid * 32 + 31;

    for (int k0 = 0; k0 <= kmax; k0 += 64) {
        {
            int r  = threadIdx.x >> 1;
            int c0 = (threadIdx.x & 1) * 32;
            const float* kp = qkv + (size_t)(b * TT + k0 + r) * (3*DD) + DD   + h * HDIM + c0;
            const float* vp = qkv + (size_t)(b * TT + k0 + r) * (3*DD) + 2*DD + h * HDIM + c0;
            #pragma unroll
            for (int i = 0; i < 8; i++) {
                *(float4*)&Kt[r][c0 + i*4] = *(const float4*)(kp + i*4);
                *(float4*)&Vt[r][c0 + i*4] = *(const float4*)(vp + i*4);
            }
        }
        __syncthreads();

        int jmaxw = warp_tmax - k0; if (jmaxw > 63) jmaxw = 63;
        int jme   = t - k0;         if (jme > 63)   jme = 63;

        for (int jt = 0; jt <= (jmaxw >> 4); jt++) {
            if (jt*16 <= jme) {
                float sc[16];
                #pragma unroll
                for (int jj = 0; jj < 16; jj++) {
                    int j = jt*16 + jj;
                    const float4* kr = (const float4*)&Kt[j][0];
                    float s = 0.0f;
                    #pragma unroll
                    for (int i = 0; i < 16; i++) {
                        float4 kk = kr[i];
                        s += qv[i].x*kk.x + qv[i].y*kk.y + qv[i].z*kk.z + qv[i].w*kk.w;
                    }
                    sc[jj] = (j <= jme) ? s * SCALE_ATT : -1e30f;
                }
                float tmax = sc[0];
                #pragma unroll
                for (int jj = 1; jj < 16; jj++) tmax = fmaxf(tmax, sc[jj]);
                float newm = fmaxf(m, tmax);
                float cor = __expf(m - newm);
                l *= cor;
                #pragma unroll
                for (int i = 0; i < 16; i++) {
                    acc[i].x *= cor; acc[i].y *= cor;
                    acc[i].z *= cor; acc[i].w *= cor;
                }
                #pragma unroll
                for (int jj = 0; jj < 16; jj++) {
                    float p = __expf(sc[jj] - newm);
                    l += p;
                    const float4* vr = (const float4*)&Vt[jt*16 + jj][0];
                    #pragma unroll
                    for (int i = 0; i < 16; i++) {
                        float4 vv = vr[i];
                        acc[i].x += p * vv.x; acc[i].y += p * vv.y;
                        acc[i].z += p * vv.z; acc[i].w += p * vv.w;
                    }
                }
                m = newm;
            }
        }
        __syncthreads();
    }

    float inv = 1.0f / l;
    size_t base = (size_t)row * DD + h * HDIM;
    #pragma unroll
    for (int i = 0; i < 16; i++) {
        float o0 = acc[i].x * inv, o1 = acc[i].y * inv;
        float o2 = acc[i].z * inv, o3 = acc[i].w * inv;
        float r0, r1, r2, r3;
        uint2 hi, lo;
        hi.x = pack2_hi(o0, o1, r0, r1);
        hi.y = pack2_hi(o2, o3, r2, r3);
        lo.x = pack2(r0, r1); lo.y = pack2(r2, r3);
        *(uint2*)(yhi + base + i*4) = hi;
        *(uint2*)(ylo + base + i*4) = lo;
    }
}

// ---------------------------------------------------------------------------
// NLL: single-pass online logsumexp
// ---------------------------------------------------------------------------
__global__ __launch_bounds__(256) void nll_kernel(
    const float* __restrict__ logits, const int* __restrict__ tgt,
    float* __restrict__ nll)
{
    __shared__ float rm[256];
    __shared__ float rs[256];
    int row = blockIdx.x;
    int tid = threadIdx.x;
    const float* lr = logits + (size_t)row * VV;

    float m = -3.4e38f, s = 0.0f;
    for (int i = tid; i < VV; i += 256) {
        float v = lr[i];
        if (v <= m) {
            s += __expf(v - m);
        } else {
            s = s * __expf(m - v) + 1.0f;
            m = v;
        }
    }
    rm[tid] = m; rs[tid] = s;
    __syncthreads();
    for (int o = 128; o > 0; o >>= 1) {
        if (tid < o) {
            float m2 = rm[tid + o], s2 = rs[tid + o];
            float M = fmaxf(rm[tid], m2);
            rs[tid] = rs[tid] * __expf(rm[tid] - M) + s2 * __expf(m2 - M);
            rm[tid] = M;
        }
        __syncthreads();
    }
    if (tid == 0) {
        float lse = rm[0] + logf(rs[0]);
        int tg = tgt[row];
        nll[row] = (tg != 0) ? (lse - lr[tg]) : 0.0f;
    }
}

__global__ __launch_bounds__(256) void loss_kernel(
    const float* __restrict__ nll, const int* __restrict__ tgt,
    float* __restrict__ out)
{
    __shared__ float s[256];
    __shared__ float c[256];
    int tid = threadIdx.x;
    float sv = 0.0f, cv = 0.0f;
    for (int i = tid; i < ROWS; i += 256) {
        sv += nll[i];
        cv += (tgt[i] != 0) ? 1.0f : 0.0f;
    }
    s[tid] = sv; c[tid] = cv; __syncthreads();
    for (int o = 128; o > 0; o >>= 1) {
        if (tid < o) { s[tid] += s[tid+o]; c[tid] += c[tid+o]; }
        __syncthreads();
    }
    if (tid == 0) out[0] = s[0] / fmaxf(c[0], 1.0f);
}

// ---------------------------------------------------------------------------
// Launcher
// ---------------------------------------------------------------------------
extern "C" void kernel_launch(void* const* d_in, const int* in_sizes, int n_in,
                              void* d_out, int out_size)
{
    const int*   idx   = (const int*)  d_in[0];
    const int*   tgt   = (const int*)  d_in[1];
    const float* tok   = (const float*)d_in[2];
    const float* pos   = (const float*)d_in[3];
    const float* ln1g  = (const float*)d_in[4];
    const float* ln1b  = (const float*)d_in[5];
    const float* wqkv  = (const float*)d_in[6];
    const float* bqkv  = (const float*)d_in[7];
    const float* wproj = (const float*)d_in[8];
    const float* bproj = (const float*)d_in[9];
    const float* ln2g  = (const float*)d_in[10];
    const float* ln2b  = (const float*)d_in[11];
    const float* w1    = (const float*)d_in[12];
    const float* b1    = (const float*)d_in[13];
    const float* w2    = (const float*)d_in[14];
    const float* b2    = (const float*)d_in[15];
    const float* lmw   = (const float*)d_in[16];

    float *px, *pqkv, *pnll, *psa, *psb;
    __nv_bfloat16 *phhi, *phlo, *pyhi, *pylo, *pmhi, *pmlo;
    __nv_bfloat16 *pwqkvhi, *pwqkvlo, *pwprojhi, *pwprojlo;
    __nv_bfloat16 *pw1hi, *pw1lo, *pw2hi, *pw2lo;
    signed char *pxq1, *pxq2, *plmq1, *plmq2;
    cudaGetSymbolAddress((void**)&px,     g_x);
    cudaGetSymbolAddress((void**)&pqkv,   g_qkv);
    cudaGetSymbolAddress((void**)&pnll,   g_nll);
    cudaGetSymbolAddress((void**)&phhi,   g_hhi);
    cudaGetSymbolAddress((void**)&phlo,   g_hlo);
    cudaGetSymbolAddress((void**)&pyhi,   g_yhi);
    cudaGetSymbolAddress((void**)&pylo,   g_ylo);
    cudaGetSymbolAddress((void**)&pmhi,   g_mhi);
    cudaGetSymbolAddress((void**)&pmlo,   g_mlo);
    cudaGetSymbolAddress((void**)&pwqkvhi,  g_wqkvThi);
    cudaGetSymbolAddress((void**)&pwqkvlo,  g_wqkvTlo);
    cudaGetSymbolAddress((void**)&pwprojhi, g_wprojThi);
    cudaGetSymbolAddress((void**)&pwprojlo, g_wprojTlo);
    cudaGetSymbolAddress((void**)&pw1hi,  g_w1Thi);
    cudaGetSymbolAddress((void**)&pw1lo,  g_w1Tlo);
    cudaGetSymbolAddress((void**)&pw2hi,  g_w2Thi);
    cudaGetSymbolAddress((void**)&pw2lo,  g_w2Tlo);
    cudaGetSymbolAddress((void**)&pxq1,   g_xq1);
    cudaGetSymbolAddress((void**)&pxq2,   g_xq2);
    cudaGetSymbolAddress((void**)&psa,    g_sa);
    cudaGetSymbolAddress((void**)&plmq1,  g_lmq1);
    cudaGetSymbolAddress((void**)&plmq2,  g_lmq2);
    cudaGetSymbolAddress((void**)&psb,    g_sb);

    cudaFuncSetAttribute((const void*)hgemm_kernel<0>,
                         cudaFuncAttributeMaxDynamicSharedMemorySize, SMEM_DYN);
    cudaFuncSetAttribute((const void*)hgemm_kernel<1>,
                         cudaFuncAttributeMaxDynamicSharedMemorySize, SMEM_DYN);
    cudaFuncSetAttribute((const void*)hgemm_kernel<2>,
                         cudaFuncAttributeMaxDynamicSharedMemorySize, SMEM_DYN);
    cudaFuncSetAttribute((const void*)igemm_kernel,
                         cudaFuncAttributeMaxDynamicSharedMemorySize, SMEM_I);

    float* out = (float*)d_out;

    // weight prep (graph-captured each launch)
    tp_kernel<<<dim3(3*DD/32, DD/32, LL), 256>>>(
        wqkv, pwqkvhi, pwqkvlo, DD, 3*DD, 3*DD, (size_t)DD*3*DD, (size_t)3*DD*DD);
    tp_kernel<<<dim3(DD/32, DD/32, LL), 256>>>(
        wproj, pwprojhi, pwprojlo, DD, DD, DD, (size_t)DD*DD, (size_t)DD*DD);
    tp_kernel<<<dim3(4*DD/32, DD/32, LL), 256>>>(
        w1, pw1hi, pw1lo, DD, 4*DD, 4*DD, (size_t)DD*4*DD, (size_t)4*DD*DD);
    tp_kernel<<<dim3(DD/32, 4*DD/32, LL), 256>>>(
        w2, pw2hi, pw2lo, 4*DD, DD, DD, (size_t)4*DD*DD, (size_t)DD*4*DD);
    colscale_kernel<<<(VPAD + 255)/256, 256>>>(lmw, psb);
    tpq_kernel<<<dim3(VPAD/32, DD/32), 256>>>(lmw, plmq1, plmq2, psb);

    embed_kernel<<<ROWS, 256>>>(idx, tok, pos, px);

    for (int l = 0; l < LL; l++) {
        ln_kernel<<<ROWS, 256>>>(px, ln1g + (size_t)l*DD, ln1b + (size_t)l*DD, phhi, phlo);
        hgemm_kernel<0><<<dim3(ROWS/128, 3*DD/128), 256, SMEM_DYN>>>(
            ROWS, 3*DD, DD, phhi, phlo,
            pwqkvhi + (size_t)l*3*DD*DD, pwqkvlo + (size_t)l*3*DD*DD,
            bqkv + (size_t)l*3*DD, nullptr, pqkv, nullptr, nullptr);
        attn_kernel<<<dim3(BB*HH, TT/128), 128>>>(pqkv, pyhi, pylo);
        hgemm_kernel<2><<<dim3(ROWS/128, DD/128), 256, SMEM_DYN>>>(
            ROWS, DD, DD, pyhi, pylo,
            pwprojhi + (size_t)l*DD*DD, pwprojlo + (size_t)l*DD*DD,
            bproj + (size_t)l*DD, px, px, nullptr, nullptr);
        ln_kernel<<<ROWS, 256>>>(px, ln2g + (size_t)l*DD, ln2b + (size_t)l*DD, phhi, phlo);
        hgemm_kernel<1><<<dim3(ROWS/128, 4*DD/128), 256, SMEM_DYN>>>(
            ROWS, 4*DD, DD, phhi, phlo,
            pw1hi + (size_t)l*4*DD*DD, pw1lo + (size_t)l*4*DD*DD,
            b1 + (size_t)l*4*DD, nullptr, nullptr, pmhi, pmlo);
        hgemm_kernel<2><<<dim3(ROWS/128, DD/128), 256, SMEM_DYN>>>(
            ROWS, DD, 4*DD, pmhi, pmlo,
            pw2hi + (size_t)l*DD*4*DD, pw2lo + (size_t)l*DD*4*DD,
            b2 + (size_t)l*DD, px, px, nullptr, nullptr);
    }

    // LM head: int8 Ozaki GEMM
    rowquant_kernel<<<ROWS, 256>>>(px, pxq1, pxq2, psa);
    igemm_kernel<<<dim3(ROWS/128, VPAD/128), 256, SMEM_I>>>(
        ROWS, VV, DD, pxq1, pxq2, plmq1, plmq2, psa, psb, out);

    // loss
    nll_kernel<<<ROWS, 256>>>(out, tgt, pnll);
    size_t nlog = (size_t)ROWS * VV;
    if ((size_t)out_size > nlog) {
        loss_kernel<<<1, 256>>>(pnll, tgt, out + nlog);
    }
}

// round 8
// speedup vs baseline: 1.2983x; 1.2983x over previous
#include <cuda_runtime.h>
#include <cuda_bf16.h>
#include <math.h>
#include <stdint.h>

// Problem constants
#define BB 4
#define TT 1024
#define DD 1024
#define HH 16
#define HDIM 64
#define LL 8
#define VV 50257
#define VPAD 50304
#define ROWS (BB*TT)            // 4096
#define SCALE_ATT 0.07216878364870322f  // 1/sqrt(192)

// ---------------------------------------------------------------------------
// Scratch (static device globals; no runtime allocation)
// ---------------------------------------------------------------------------
__device__ float g_x   [ (size_t)ROWS * DD     ];   // residual stream (fp32)
__device__ float g_qkv [ (size_t)ROWS * 3 * DD ];   // qkv (fp32)
__device__ float g_nll [ ROWS ];
// bf16 hi/lo split activations
__device__ __nv_bfloat16 g_hhi [ (size_t)ROWS * DD ];
__device__ __nv_bfloat16 g_hlo [ (size_t)ROWS * DD ];
__device__ __nv_bfloat16 g_yhi [ (size_t)ROWS * DD ];
__device__ __nv_bfloat16 g_ylo [ (size_t)ROWS * DD ];
__device__ __nv_bfloat16 g_mhi [ (size_t)ROWS * 4 * DD ];
__device__ __nv_bfloat16 g_mlo [ (size_t)ROWS * 4 * DD ];
__device__ __nv_bfloat16 g_xhi [ (size_t)ROWS * DD ];
__device__ __nv_bfloat16 g_xlo [ (size_t)ROWS * DD ];
// bf16 hi/lo split transposed weights ([N,K] row-major)
__device__ __nv_bfloat16 g_wqkvThi [ (size_t)LL * 3*DD * DD ];
__device__ __nv_bfloat16 g_wqkvTlo [ (size_t)LL * 3*DD * DD ];
__device__ __nv_bfloat16 g_wprojThi[ (size_t)LL * DD * DD ];
__device__ __nv_bfloat16 g_wprojTlo[ (size_t)LL * DD * DD ];
__device__ __nv_bfloat16 g_w1Thi   [ (size_t)LL * 4*DD * DD ];
__device__ __nv_bfloat16 g_w1Tlo   [ (size_t)LL * 4*DD * DD ];
__device__ __nv_bfloat16 g_w2Thi   [ (size_t)LL * DD * 4*DD ];
__device__ __nv_bfloat16 g_w2Tlo   [ (size_t)LL * DD * 4*DD ];
__device__ __nv_bfloat16 g_lmwThi  [ (size_t)VPAD * DD ];
__device__ __nv_bfloat16 g_lmwTlo  [ (size_t)VPAD * DD ];

// ---------------------------------------------------------------------------
// helpers
// ---------------------------------------------------------------------------
__device__ __forceinline__ uint32_t smem_u32(const void* p) {
    uint32_t a;
    asm("{ .reg .u64 t; cvta.to.shared.u64 t, %1; cvt.u32.u64 %0, t; }"
        : "=r"(a) : "l"(p));
    return a;
}
__device__ __forceinline__ uint32_t pack2_hi(float x, float y, float& rx, float& ry) {
    __nv_bfloat16 hx = __float2bfloat16_rn(x);
    __nv_bfloat16 hy = __float2bfloat16_rn(y);
    rx = x - __bfloat162float(hx);
    ry = y - __bfloat162float(hy);
    return (uint32_t)__bfloat16_as_ushort(hx) | ((uint32_t)__bfloat16_as_ushort(hy) << 16);
}
__device__ __forceinline__ uint32_t pack2(float x, float y) {
    __nv_bfloat16 hx = __float2bfloat16_rn(x);
    __nv_bfloat16 hy = __float2bfloat16_rn(y);
    return (uint32_t)__bfloat16_as_ushort(hx) | ((uint32_t)__bfloat16_as_ushort(hy) << 16);
}

#define MMA_BF16(d, a, b) \
    asm volatile("mma.sync.aligned.m16n8k16.row.col.f32.bf16.bf16.f32 " \
        "{%0,%1,%2,%3}, {%4,%5,%6,%7}, {%8,%9}, {%0,%1,%2,%3};" \
        : "+f"((d)[0]), "+f"((d)[1]), "+f"((d)[2]), "+f"((d)[3]) \
        : "r"((a)[0]), "r"((a)[1]), "r"((a)[2]), "r"((a)[3]), \
          "r"((b)[0]), "r"((b)[1]))

#define LDSM4(r0, r1, r2, r3, addr) \
    asm volatile("ldmatrix.sync.aligned.m8n8.x4.shared.b16 {%0,%1,%2,%3}, [%4];" \
        : "=r"(r0), "=r"(r1), "=r"(r2), "=r"(r3) : "r"(addr))

__device__ __forceinline__ void cp16(uint32_t d, const void* g) {
    asm volatile("cp.async.cg.shared.global [%0], [%1], 16;" :: "r"(d), "l"(g));
}
#define CP_COMMIT() asm volatile("cp.async.commit_group;" ::: "memory")
#define CP_WAIT0()  asm volatile("cp.async.wait_group 0;" ::: "memory")
#define CP_WAIT1()  asm volatile("cp.async.wait_group 1;" ::: "memory")

// ---------------------------------------------------------------------------
// bf16-split tensor GEMM: C = A @ Bt^T, A/B pre-split bf16 hi/lo.
// CTA tile 128x128, K-chunk 32, 2-stage cp.async, 512 threads.
// Warp grid 4x4, warp tile 32x32 -> 4 warps/SMSP for MMA latency hiding.
// EPI: 0=bias->f32, 1=bias+relu->bf16 split, 2=bias+residual->f32.
// smem per buffer: Ahi|Alo|Bhi|Blo, each 128 rows x 80B.
// ---------------------------------------------------------------------------
#define TILEB 10240
#define BUFB  (4*TILEB)        // 40960
#define SMEM_DYN (2*BUFB)      // 81920; epilogue Cs (128*132*4=67584) fits

template<int EPI>
__global__ __launch_bounds__(512) void hgemm_kernel(
    int M, int N, int K,
    const __nv_bfloat16* __restrict__ Ahi, const __nv_bfloat16* __restrict__ Alo,
    const __nv_bfloat16* __restrict__ Bhi, const __nv_bfloat16* __restrict__ Blo,
    const float* __restrict__ bias, const float* __restrict__ res,
    float* __restrict__ C,
    __nv_bfloat16* __restrict__ Chi, __nv_bfloat16* __restrict__ Clo)
{
    extern __shared__ __align__(128) char smem[];
    const uint32_t sb = smem_u32(smem);
    const int tid  = threadIdx.x;
    const int wid  = tid >> 5;
    const int lane = tid & 31;
    const int mbase = blockIdx.x * 128;
    const int nbase = blockIdx.y * 128;
    const int warp_m = wid & 3;          // 0..3 (32 rows each)
    const int warp_n = wid >> 2;         // 0..3 (32 cols each)
    const int g = lane >> 2;
    const int q = lane & 3;

    // ldmatrix lane-address offsets (within a buffer)
    const uint32_t aoff = (uint32_t)(warp_m*32 + (lane & 15)) * 80
                        + ((lane >> 4) & 1) * 16;
    const uint32_t boff = 2*TILEB
                        + (uint32_t)(warp_n*32 + (lane & 7) + ((lane >> 4) & 1)*8) * 80
                        + ((lane >> 3) & 1) * 16;

    float acc[2][4][4];
    #pragma unroll
    for (int m = 0; m < 2; m++)
        #pragma unroll
        for (int n = 0; n < 4; n++)
            #pragma unroll
            for (int r = 0; r < 4; r++) acc[m][n][r] = 0.0f;

    const int nch = K >> 5;

    // async loader: 4 tiles x 512 transfers, one per thread per tile
    auto issue = [&](uint32_t dstbase, int k0) {
        const int row = tid >> 2, seg = tid & 3;
        const uint32_t doff = (uint32_t)row*80 + seg*16;
        const int soff = k0 + seg*8;
        cp16(dstbase + doff,           Ahi + (size_t)(mbase+row)*K + soff);
        cp16(dstbase + TILEB + doff,   Alo + (size_t)(mbase+row)*K + soff);
        cp16(dstbase + 2*TILEB + doff, Bhi + (size_t)(nbase+row)*K + soff);
        cp16(dstbase + 3*TILEB + doff, Blo + (size_t)(nbase+row)*K + soff);
    };

    issue(sb, 0);
    CP_COMMIT();

    for (int it = 0; it < nch; it++) {
        if (it + 1 < nch) {
            issue(sb + ((it+1) & 1) * BUFB, (it+1) << 5);
            CP_COMMIT();
            CP_WAIT1();
        } else {
            CP_WAIT0();
        }
        __syncthreads();

        const uint32_t bufu = sb + (it & 1) * BUFB;

        #pragma unroll
        for (int ks = 0; ks < 32; ks += 16) {
            uint32_t ah[2][4], al[2][4], bh[4][2], bl[4][2];
            #pragma unroll
            for (int m = 0; m < 2; m++) {
                uint32_t ad = bufu + aoff + m*(16*80) + ks*2;
                LDSM4(ah[m][0], ah[m][1], ah[m][2], ah[m][3], ad);
                LDSM4(al[m][0], al[m][1], al[m][2], al[m][3], ad + TILEB);
            }
            #pragma unroll
            for (int n2 = 0; n2 < 2; n2++) {
                uint32_t bd = bufu + boff + n2*(16*80) + ks*2;
                uint32_t r0, r1, r2, r3;
                LDSM4(r0, r1, r2, r3, bd);
                bh[n2*2][0] = r0; bh[n2*2][1] = r1;
                bh[n2*2+1][0] = r2; bh[n2*2+1][1] = r3;
                LDSM4(r0, r1, r2, r3, bd + TILEB);
                bl[n2*2][0] = r0; bl[n2*2][1] = r1;
                bl[n2*2+1][0] = r2; bl[n2*2+1][1] = r3;
            }
            #pragma unroll
            for (int m = 0; m < 2; m++)
                #pragma unroll
                for (int n = 0; n < 4; n++) {
                    MMA_BF16(acc[m][n], ah[m], bh[n]);
                    MMA_BF16(acc[m][n], ah[m], bl[n]);
                    MMA_BF16(acc[m][n], al[m], bh[n]);
                }
        }
        __syncthreads();
    }

    // epilogue: stage through smem for coalesced writes
    float* Cs = (float*)smem;   // [128][132]
    #pragma unroll
    for (int m = 0; m < 2; m++) {
        int r0 = warp_m*32 + m*16 + g;
        #pragma unroll
        for (int n = 0; n < 4; n++) {
            int col = warp_n*32 + n*8 + 2*q;
            Cs[r0*132 + col]       = acc[m][n][0];
            Cs[r0*132 + col + 1]   = acc[m][n][1];
            Cs[(r0+8)*132 + col]   = acc[m][n][2];
            Cs[(r0+8)*132 + col+1] = acc[m][n][3];
        }
    }
    __syncthreads();

    if (EPI == 1) {
        #pragma unroll
        for (int i = 0; i < 8; i++) {
            int u = tid + i*512;
            int row = u >> 5, c4 = (u & 31) * 4;
            int col = nbase + c4;
            float v0 = Cs[row*132 + c4 + 0] + bias[col];
            float v1 = Cs[row*132 + c4 + 1] + bias[col+1];
            float v2 = Cs[row*132 + c4 + 2] + bias[col+2];
            float v3 = Cs[row*132 + c4 + 3] + bias[col+3];
            v0 = fmaxf(v0, 0.f); v1 = fmaxf(v1, 0.f);
            v2 = fmaxf(v2, 0.f); v3 = fmaxf(v3, 0.f);
            float r0, r1, r2, r3;
            uint2 hi, lo;
            hi.x = pack2_hi(v0, v1, r0, r1);
            hi.y = pack2_hi(v2, v3, r2, r3);
            lo.x = pack2(r0, r1); lo.y = pack2(r2, r3);
            size_t off = (size_t)(mbase+row)*N + col;
            *(uint2*)(Chi + off) = hi;
            *(uint2*)(Clo + off) = lo;
        }
    } else if ((N & 3) == 0) {
        #pragma unroll
        for (int i = 0; i < 8; i++) {
            int u = tid + i*512;
            int row = u >> 5, c4 = (u & 31) * 4;
            int col = nbase + c4;
            float v0 = Cs[row*132 + c4 + 0];
            float v1 = Cs[row*132 + c4 + 1];
            float v2 = Cs[row*132 + c4 + 2];
            float v3 = Cs[row*132 + c4 + 3];
            if (bias) { v0 += bias[col]; v1 += bias[col+1]; v2 += bias[col+2]; v3 += bias[col+3]; }
            if (EPI == 2) {
                const float4 rv = *(const float4*)(res + (size_t)(mbase+row)*N + col);
                v0 += rv.x; v1 += rv.y; v2 += rv.z; v3 += rv.w;
            }
            *(float4*)(C + (size_t)(mbase+row)*N + col) = make_float4(v0, v1, v2, v3);
        }
    } else {
        #pragma unroll
        for (int i = 0; i < 8; i++) {
            int u = tid + i*512;
            int row = u >> 5, c4 = (u & 31) * 4;
            float* crow = C + (size_t)(mbase+row)*N;
            #pragma unroll
            for (int j = 0; j < 4; j++) {
                int col = nbase + c4 + j;
                if (col < N) {
                    float v = Cs[row*132 + c4 + j];
                    if (bias) v += bias[col];
                    if (EPI == 2) v += res[(size_t)(mbase+row)*N + col];
                    crow[col] = v;
                }
            }
        }
    }
}

// ---------------------------------------------------------------------------
// Tiled transpose + bf16 split: in [K,N] -> outhi/outlo [Npad,K], zero-pad
// ---------------------------------------------------------------------------
__global__ __launch_bounds__(256) void tp_kernel(
    const float* __restrict__ in,
    __nv_bfloat16* __restrict__ outhi, __nv_bfloat16* __restrict__ outlo,
    int K, int N, int Npad, size_t inStride, size_t outStride)
{
    __shared__ float t[32][33];
    const float* ip = in + blockIdx.z * inStride;
    __nv_bfloat16* ohi = outhi + blockIdx.z * outStride;
    __nv_bfloat16* olo = outlo + blockIdx.z * outStride;
    int n0 = blockIdx.x * 32, k0 = blockIdx.y * 32;
    int tx = threadIdx.x & 31, ty = threadIdx.x >> 5;
    #pragma unroll
    for (int j = ty; j < 32; j += 8) {
        int k = k0 + j, n = n0 + tx;
        t[j][tx] = (k < K && n < N) ? ip[(size_t)k * N + n] : 0.0f;
    }
    __syncthreads();
    #pragma unroll
    for (int j = ty; j < 32; j += 8) {
        int n = n0 + j, k = k0 + tx;
        if (n < Npad && k < K) {
            float v = t[tx][j];
            __nv_bfloat16 h = __float2bfloat16_rn(v);
            __nv_bfloat16 l = __float2bfloat16_rn(v - __bfloat162float(h));
            ohi[(size_t)n * K + k] = h;
            olo[(size_t)n * K + k] = l;
        }
    }
}

// ---------------------------------------------------------------------------
// Elementwise bf16 split of a fp32 tensor (for LM-head input)
// ---------------------------------------------------------------------------
__global__ __launch_bounds__(256) void split_kernel(
    const float* __restrict__ x,
    __nv_bfloat16* __restrict__ xhi, __nv_bfloat16* __restrict__ xlo)
{
    size_t i = ((size_t)blockIdx.x * 256 + threadIdx.x) * 4;
    float4 v = *(const float4*)(x + i);
    float r0, r1, r2, r3;
    uint2 hi, lo;
    hi.x = pack2_hi(v.x, v.y, r0, r1);
    hi.y = pack2_hi(v.z, v.w, r2, r3);
    lo.x = pack2(r0, r1); lo.y = pack2(r2, r3);
    *(uint2*)(xhi + i) = hi;
    *(uint2*)(xlo + i) = lo;
}

// ---------------------------------------------------------------------------
// Embedding
// ---------------------------------------------------------------------------
__global__ __launch_bounds__(256) void embed_kernel(
    const int* __restrict__ idx, const float* __restrict__ tok,
    const float* __restrict__ pos, float* __restrict__ x)
{
    int row = blockIdx.x;
    int t   = row & (TT - 1);
    int id  = idx[row];
    const float4* tp = (const float4*)(tok + (size_t)id * DD);
    const float4* pp = (const float4*)(pos + (size_t)t  * DD);
    float4*       xp = (float4*)(x + (size_t)row * DD);
    int i = threadIdx.x;
    float4 a = tp[i], b = pp[i];
    a.x += b.x; a.y += b.y; a.z += b.z; a.w += b.w;
    xp[i] = a;
}

// ---------------------------------------------------------------------------
// LayerNorm -> bf16 hi/lo split output
// ---------------------------------------------------------------------------
__global__ __launch_bounds__(256) void ln_kernel(
    const float* __restrict__ x, const float* __restrict__ g,
    const float* __restrict__ b,
    __nv_bfloat16* __restrict__ ohi, __nv_bfloat16* __restrict__ olo)
{
    __shared__ float s1[256];
    __shared__ float s2[256];
    int row = blockIdx.x;
    int tid = threadIdx.x;
    float4 v = ((const float4*)(x + (size_t)row * DD))[tid];
    float s  = v.x + v.y + v.z + v.w;
    float ss = v.x*v.x + v.y*v.y + v.z*v.z + v.w*v.w;
    s1[tid] = s; s2[tid] = ss;
    __syncthreads();
    for (int o = 128; o > 0; o >>= 1) {
        if (tid < o) { s1[tid] += s1[tid+o]; s2[tid] += s2[tid+o]; }
        __syncthreads();
    }
    float mu   = s1[0] * (1.0f / DD);
    float var  = s2[0] * (1.0f / DD) - mu * mu;
    float rstd = rsqrtf(var + 1e-5f);
    float4 gv = ((const float4*)g)[tid];
    float4 bv = ((const float4*)b)[tid];
    float o0 = (v.x - mu) * rstd * gv.x + bv.x;
    float o1 = (v.y - mu) * rstd * gv.y + bv.y;
    float o2 = (v.z - mu) * rstd * gv.z + bv.z;
    float o3 = (v.w - mu) * rstd * gv.w + bv.w;
    float r0, r1, r2, r3;
    uint2 hi, lo;
    hi.x = pack2_hi(o0, o1, r0, r1);
    hi.y = pack2_hi(o2, o3, r2, r3);
    lo.x = pack2(r0, r1); lo.y = pack2(r2, r3);
    size_t off = (size_t)row * DD + tid * 4;
    *(uint2*)(ohi + off) = hi;
    *(uint2*)(olo + off) = lo;
}

// ---------------------------------------------------------------------------
// Fused causal attention: one thread per query, branchless 16-key score
// tiles with online softmax. Block = 128 threads/queries. Grid (B*H, T/128).
// ---------------------------------------------------------------------------
__global__ __launch_bounds__(128) void attn_kernel(
    const float* __restrict__ qkv,
    __nv_bfloat16* __restrict__ yhi, __nv_bfloat16* __restrict__ ylo)
{
    const int bh = blockIdx.x;
    const int b  = bh >> 4;
    const int h  = bh & (HH - 1);
    const int t  = blockIdx.y * 128 + threadIdx.x;
    const int row = b * TT + t;
    const int wid = threadIdx.x >> 5;

    __shared__ float Kt[64][HDIM];
    __shared__ float Vt[64][HDIM];

    float4 qv[16];
    {
        const float4* qp = (const float4*)(qkv + (size_t)row * (3*DD) + h * HDIM);
        #pragma unroll
        for (int i = 0; i < 16; i++) qv[i] = qp[i];
    }

    float4 acc[16];
    #pragma unroll
    for (int i = 0; i < 16; i++) acc[i] = make_float4(0.f, 0.f, 0.f, 0.f);
    float m = -1e30f, l = 0.0f;

    const int kmax = blockIdx.y * 128 + 127;
    const int warp_tmax = blockIdx.y * 128 + wid * 32 + 31;

    for (int k0 = 0; k0 <= kmax; k0 += 64) {
        {
            int r  = threadIdx.x >> 1;
            int c0 = (threadIdx.x & 1) * 32;
            const float* kp = qkv + (size_t)(b * TT + k0 + r) * (3*DD) + DD   + h * HDIM + c0;
            const float* vp = qkv + (size_t)(b * TT + k0 + r) * (3*DD) + 2*DD + h * HDIM + c0;
            #pragma unroll
            for (int i = 0; i < 8; i++) {
                *(float4*)&Kt[r][c0 + i*4] = *(const float4*)(kp + i*4);
                *(float4*)&Vt[r][c0 + i*4] = *(const float4*)(vp + i*4);
            }
        }
        __syncthreads();

        int jmaxw = warp_tmax - k0; if (jmaxw > 63) jmaxw = 63;
        int jme   = t - k0;         if (jme > 63)   jme = 63;

        for (int jt = 0; jt <= (jmaxw >> 4); jt++) {
            if (jt*16 <= jme) {
                float sc[16];
                #pragma unroll
                for (int jj = 0; jj < 16; jj++) {
                    int j = jt*16 + jj;
                    const float4* kr = (const float4*)&Kt[j][0];
                    float s = 0.0f;
                    #pragma unroll
                    for (int i = 0; i < 16; i++) {
                        float4 kk = kr[i];
                        s += qv[i].x*kk.x + qv[i].y*kk.y + qv[i].z*kk.z + qv[i].w*kk.w;
                    }
                    sc[jj] = (j <= jme) ? s * SCALE_ATT : -1e30f;
                }
                float tmax = sc[0];
                #pragma unroll
                for (int jj = 1; jj < 16; jj++) tmax = fmaxf(tmax, sc[jj]);
                float newm = fmaxf(m, tmax);
                float cor = __expf(m - newm);
                l *= cor;
                #pragma unroll
                for (int i = 0; i < 16; i++) {
                    acc[i].x *= cor; acc[i].y *= cor;
                    acc[i].z *= cor; acc[i].w *= cor;
                }
                #pragma unroll
                for (int jj = 0; jj < 16; jj++) {
                    float p = __expf(sc[jj] - newm);
                    l += p;
                    const float4* vr = (const float4*)&Vt[jt*16 + jj][0];
                    #pragma unroll
                    for (int i = 0; i < 16; i++) {
                        float4 vv = vr[i];
                        acc[i].x += p * vv.x; acc[i].y += p * vv.y;
                        acc[i].z += p * vv.z; acc[i].w += p * vv.w;
                    }
                }
                m = newm;
            }
        }
        __syncthreads();
    }

    float inv = 1.0f / l;
    size_t base = (size_t)row * DD + h * HDIM;
    #pragma unroll
    for (int i = 0; i < 16; i++) {
        float o0 = acc[i].x * inv, o1 = acc[i].y * inv;
        float o2 = acc[i].z * inv, o3 = acc[i].w * inv;
        float r0, r1, r2, r3;
        uint2 hi, lo;
        hi.x = pack2_hi(o0, o1, r0, r1);
        hi.y = pack2_hi(o2, o3, r2, r3);
        lo.x = pack2(r0, r1); lo.y = pack2(r2, r3);
        *(uint2*)(yhi + base + i*4) = hi;
        *(uint2*)(ylo + base + i*4) = lo;
    }
}

// ---------------------------------------------------------------------------
// NLL: single-pass online logsumexp
// ---------------------------------------------------------------------------
__global__ __launch_bounds__(256) void nll_kernel(
    const float* __restrict__ logits, const int* __restrict__ tgt,
    float* __restrict__ nll)
{
    __shared__ float rm[256];
    __shared__ float rs[256];
    int row = blockIdx.x;
    int tid = threadIdx.x;
    const float* lr = logits + (size_t)row * VV;

    float m = -3.4e38f, s = 0.0f;
    for (int i = tid; i < VV; i += 256) {
        float v = lr[i];
        if (v <= m) {
            s += __expf(v - m);
        } else {
            s = s * __expf(m - v) + 1.0f;
            m = v;
        }
    }
    rm[tid] = m; rs[tid] = s;
    __syncthreads();
    for (int o = 128; o > 0; o >>= 1) {
        if (tid < o) {
            float m2 = rm[tid + o], s2 = rs[tid + o];
            float M = fmaxf(rm[tid], m2);
            rs[tid] = rs[tid] * __expf(rm[tid] - M) + s2 * __expf(m2 - M);
            rm[tid] = M;
        }
        __syncthreads();
    }
    if (tid == 0) {
        float lse = rm[0] + logf(rs[0]);
        int tg = tgt[row];
        nll[row] = (tg != 0) ? (lse - lr[tg]) : 0.0f;
    }
}

__global__ __launch_bounds__(256) void loss_kernel(
    const float* __restrict__ nll, const int* __restrict__ tgt,
    float* __restrict__ out)
{
    __shared__ float s[256];
    __shared__ float c[256];
    int tid = threadIdx.x;
    float sv = 0.0f, cv = 0.0f;
    for (int i = tid; i < ROWS; i += 256) {
        sv += nll[i];
        cv += (tgt[i] != 0) ? 1.0f : 0.0f;
    }
    s[tid] = sv; c[tid] = cv; __syncthreads();
    for (int o = 128; o > 0; o >>= 1) {
        if (tid < o) { s[tid] += s[tid+o]; c[tid] += c[tid+o]; }
        __syncthreads();
    }
    if (tid == 0) out[0] = s[0] / fmaxf(c[0], 1.0f);
}

// ---------------------------------------------------------------------------
// Launcher
// ---------------------------------------------------------------------------
extern "C" void kernel_launch(void* const* d_in, const int* in_sizes, int n_in,
                              void* d_out, int out_size)
{
    const int*   idx   = (const int*)  d_in[0];
    const int*   tgt   = (const int*)  d_in[1];
    const float* tok   = (const float*)d_in[2];
    const float* pos   = (const float*)d_in[3];
    const float* ln1g  = (const float*)d_in[4];
    const float* ln1b  = (const float*)d_in[5];
    const float* wqkv  = (const float*)d_in[6];
    const float* bqkv  = (const float*)d_in[7];
    const float* wproj = (const float*)d_in[8];
    const float* bproj = (const float*)d_in[9];
    const float* ln2g  = (const float*)d_in[10];
    const float* ln2b  = (const float*)d_in[11];
    const float* w1    = (const float*)d_in[12];
    const float* b1    = (const float*)d_in[13];
    const float* w2    = (const float*)d_in[14];
    const float* b2    = (const float*)d_in[15];
    const float* lmw   = (const float*)d_in[16];

    float *px, *pqkv, *pnll;
    __nv_bfloat16 *phhi, *phlo, *pyhi, *pylo, *pmhi, *pmlo, *pxhi, *pxlo;
    __nv_bfloat16 *pwqkvhi, *pwqkvlo, *pwprojhi, *pwprojlo;
    __nv_bfloat16 *pw1hi, *pw1lo, *pw2hi, *pw2lo, *plmwhi, *plmwlo;
    cudaGetSymbolAddress((void**)&px,     g_x);
    cudaGetSymbolAddress((void**)&pqkv,   g_qkv);
    cudaGetSymbolAddress((void**)&pnll,   g_nll);
    cudaGetSymbolAddress((void**)&phhi,   g_hhi);
    cudaGetSymbolAddress((void**)&phlo,   g_hlo);
    cudaGetSymbolAddress((void**)&pyhi,   g_yhi);
    cudaGetSymbolAddress((void**)&pylo,   g_ylo);
    cudaGetSymbolAddress((void**)&pmhi,   g_mhi);
    cudaGetSymbolAddress((void**)&pmlo,   g_mlo);
    cudaGetSymbolAddress((void**)&pxhi,   g_xhi);
    cudaGetSymbolAddress((void**)&pxlo,   g_xlo);
    cudaGetSymbolAddress((void**)&pwqkvhi,  g_wqkvThi);
    cudaGetSymbolAddress((void**)&pwqkvlo,  g_wqkvTlo);
    cudaGetSymbolAddress((void**)&pwprojhi, g_wprojThi);
    cudaGetSymbolAddress((void**)&pwprojlo, g_wprojTlo);
    cudaGetSymbolAddress((void**)&pw1hi,  g_w1Thi);
    cudaGetSymbolAddress((void**)&pw1lo,  g_w1Tlo);
    cudaGetSymbolAddress((void**)&pw2hi,  g_w2Thi);
    cudaGetSymbolAddress((void**)&pw2lo,  g_w2Tlo);
    cudaGetSymbolAddress((void**)&plmwhi, g_lmwThi);
    cudaGetSymbolAddress((void**)&plmwlo, g_lmwTlo);

    cudaFuncSetAttribute((const void*)hgemm_kernel<0>,
                         cudaFuncAttributeMaxDynamicSharedMemorySize, SMEM_DYN);
    cudaFuncSetAttribute((const void*)hgemm_kernel<1>,
                         cudaFuncAttributeMaxDynamicSharedMemorySize, SMEM_DYN);
    cudaFuncSetAttribute((const void*)hgemm_kernel<2>,
                         cudaFuncAttributeMaxDynamicSharedMemorySize, SMEM_DYN);

    float* out = (float*)d_out;

    // weight transposes + bf16 split (graph-captured each launch)
    tp_kernel<<<dim3(3*DD/32, DD/32, LL), 256>>>(
        wqkv, pwqkvhi, pwqkvlo, DD, 3*DD, 3*DD, (size_t)DD*3*DD, (size_t)3*DD*DD);
    tp_kernel<<<dim3(DD/32, DD/32, LL), 256>>>(
        wproj, pwprojhi, pwprojlo, DD, DD, DD, (size_t)DD*DD, (size_t)DD*DD);
    tp_kernel<<<dim3(4*DD/32, DD/32, LL), 256>>>(
        w1, pw1hi, pw1lo, DD, 4*DD, 4*DD, (size_t)DD*4*DD, (size_t)4*DD*DD);
    tp_kernel<<<dim3(DD/32, 4*DD/32, LL), 256>>>(
        w2, pw2hi, pw2lo, 4*DD, DD, DD, (size_t)4*DD*DD, (size_t)DD*4*DD);
    tp_kernel<<<dim3(VPAD/32, DD/32, 1), 256>>>(
        lmw, plmwhi, plmwlo, DD, VV, VPAD, 0, 0);

    embed_kernel<<<ROWS, 256>>>(idx, tok, pos, px);

    for (int l = 0; l < LL; l++) {
        ln_kernel<<<ROWS, 256>>>(px, ln1g + (size_t)l*DD, ln1b + (size_t)l*DD, phhi, phlo);
        hgemm_kernel<0><<<dim3(ROWS/128, 3*DD/128), 512, SMEM_DYN>>>(
            ROWS, 3*DD, DD, phhi, phlo,
            pwqkvhi + (size_t)l*3*DD*DD, pwqkvlo + (size_t)l*3*DD*DD,
            bqkv + (size_t)l*3*DD, nullptr, pqkv, nullptr, nullptr);
        attn_kernel<<<dim3(BB*HH, TT/128), 128>>>(pqkv, pyhi, pylo);
        hgemm_kernel<2><<<dim3(ROWS/128, DD/128), 512, SMEM_DYN>>>(
            ROWS, DD, DD, pyhi, pylo,
            pwprojhi + (size_t)l*DD*DD, pwprojlo + (size_t)l*DD*DD,
            bproj + (size_t)l*DD, px, px, nullptr, nullptr);
        ln_kernel<<<ROWS, 256>>>(px, ln2g + (size_t)l*DD, ln2b + (size_t)l*DD, phhi, phlo);
        hgemm_kernel<1><<<dim3(ROWS/128, 4*DD/128), 512, SMEM_DYN>>>(
            ROWS, 4*DD, DD, phhi, phlo,
            pw1hi + (size_t)l*4*DD*DD, pw1lo + (size_t)l*4*DD*DD,
            b1 + (size_t)l*4*DD, nullptr, nullptr, pmhi, pmlo);
        hgemm_kernel<2><<<dim3(ROWS/128, DD/128), 512, SMEM_DYN>>>(
            ROWS, DD, 4*DD, pmhi, pmlo,
            pw2hi + (size_t)l*DD*4*DD, pw2lo + (size_t)l*DD*4*DD,
            b2 + (size_t)l*DD, px, px, nullptr, nullptr);
    }

    // split residual stream for LM head, then logits = x @ lm_w
    split_kernel<<<ROWS, 256>>>(px, pxhi, pxlo);
    hgemm_kernel<0><<<dim3(ROWS/128, VPAD/128), 512, SMEM_DYN>>>(
        ROWS, VV, DD, pxhi, pxlo, plmwhi, plmwlo,
        nullptr, nullptr, out, nullptr, nullptr);

    // loss
    nll_kernel<<<ROWS, 256>>>(out, tgt, pnll);
    size_t nlog = (size_t)ROWS * VV;
    if ((size_t)out_size > nlog) {
        loss_kernel<<<1, 256>>>(pnll, tgt, out + nlog);
    }
}